// round 13
// baseline (speedup 1.0000x reference)
#include <cuda_runtime.h>

#define NB 64
#define TD 2048
#define TE 512
#define G_STEPS 20000
#define LN_GAMMA (-5.0001250041667e-05)   // ln(0.99995)
#define LOG2E 1.4426950408889634
#define GRID 1184                         // 148 SMs x 8 blocks
#define CHUNK_SHIFT 3                     // 8 rows per unit
#define CHUNKS_PER_B (TD >> CHUNK_SHIFT)  // 256
#define NCHUNK (NB * CHUNKS_PER_B)        // 16384

__device__ float g_partial[GRID];
__device__ unsigned int g_ticket = 0;     // self-resetting, graph-replay safe

__device__ __forceinline__ float ex2a(float x) {
    float r; asm("ex2.approx.f32 %0, %1;" : "=f"(r) : "f"(x)); return r;
}

__device__ __forceinline__ void gal_acc(float& facc, float4 v, float y,
                                        float a0, float a1, float a2, float a3,
                                        float m1, float m2, float m3, float kneg)
{
    const float d0 = a0 - y, d1 = a1 - y, d2 = a2 - y, d3 = a3 - y;
    const float w0 = 1.0f - ex2a(d0 * d0 * kneg);
    const float w1 = 1.0f - ex2a(d1 * d1 * kneg);
    const float w2 = 1.0f - ex2a(d2 * d2 * kneg);
    const float w3 = 1.0f - ex2a(d3 * d3 * kneg);
    facc = fmaf(w0, v.x, facc);
    facc = fmaf(w1, v.y * m1, facc);
    facc = fmaf(w2, v.z * m2, facc);
    facc = fmaf(w3, v.w * m3, facc);
}

__global__ void __launch_bounds__(256, 8) gal_main_kernel(
    const float* __restrict__ A,      // [NB, TD, TE]
    const int*   __restrict__ inL,    // [NB]
    const int*   __restrict__ tgtL,   // [NB]
    const int*   __restrict__ gstep,  // [1]
    float*       __restrict__ out)    // [1]
{
    __shared__ float s_invL[NB], s_invF[NB], s_scale[NB];
    __shared__ int   s_L[NB], s_F[NB];
    __shared__ float warpsum[8];
    __shared__ int   s_last;

    const int tid = threadIdx.x;
    if (tid < NB) {
        const int L = inL[tid];
        const int F = tgtL[tid];
        s_L[tid] = L;
        s_F[tid] = F;
        s_invL[tid]  = 1.0f / (float)L;
        s_invF[tid]  = 1.0f / (float)F;
        s_scale[tid] = 1.0f / ((float)F * (float)NB);
    }
    __syncthreads();

    float partial = 0.0f;
    const int step = *gstep;

    if (step <= G_STEPS) {
        const double gd = exp((double)step * LN_GAMMA);
        const float kneg = (float)(-(0.5 / (gd * gd)) * LOG2E);

        const int half = tid >> 7;            // 0/1: row parity within the unit
        const int cidx = (tid & 127) << 2;    // float4 column start
        const float fc0 = (float)cidx;

        for (int ch = blockIdx.x; ch < NCHUNK; ch += GRID) {
            const int b  = ch >> 8;
            const int r0 = (ch & (CHUNKS_PER_B - 1)) << CHUNK_SHIFT;
            const int F = s_F[b];
            if (r0 >= F) continue;
            const int L = s_L[b];
            if (cidx >= L) continue;

            const float invL = s_invL[b];
            const float invF = s_invF[b];
            const float a0 = fc0 * invL;
            const float a1 = (fc0 + 1.0f) * invL;
            const float a2 = (fc0 + 2.0f) * invL;
            const float a3 = (fc0 + 3.0f) * invL;
            const float m1 = (cidx + 1 < L) ? 1.0f : 0.0f;
            const float m2 = (cidx + 2 < L) ? 1.0f : 0.0f;
            const float m3 = (cidx + 3 < L) ? 1.0f : 0.0f;

            const int rows = min(8, F - r0);
            const float* p = A + ((size_t)b << 20) + ((size_t)(r0 + half) << 9) + cidx;
            const float y0 = (float)(r0 + half) * invF;
            const float ys = 2.0f * invF;

            float facc = 0.0f;
            if (rows == 8) {
                // fast path: 4 independent float4 loads front-batched (MLP 4)
                const float4 v0 = __ldg((const float4*)(p));
                const float4 v1 = __ldg((const float4*)(p + 1024));
                const float4 v2 = __ldg((const float4*)(p + 2048));
                const float4 v3 = __ldg((const float4*)(p + 3072));
                gal_acc(facc, v0, y0,            a0, a1, a2, a3, m1, m2, m3, kneg);
                gal_acc(facc, v1, y0 + ys,       a0, a1, a2, a3, m1, m2, m3, kneg);
                gal_acc(facc, v2, y0 + 2.f*ys,   a0, a1, a2, a3, m1, m2, m3, kneg);
                gal_acc(facc, v3, y0 + 3.f*ys,   a0, a1, a2, a3, m1, m2, m3, kneg);
            } else {
                #pragma unroll
                for (int q = 0; q < 4; ++q) {
                    if (half + 2 * q < rows) {
                        const float4 v = __ldg((const float4*)(p + q * 1024));
                        gal_acc(facc, v, y0 + (float)q * ys,
                                a0, a1, a2, a3, m1, m2, m3, kneg);
                    }
                }
            }
            partial = fmaf(facc, s_scale[b], partial);
        }
    }

    // block reduction
    #pragma unroll
    for (int o = 16; o > 0; o >>= 1)
        partial += __shfl_down_sync(0xffffffffu, partial, o);
    const int wid = tid >> 5, lid = tid & 31;
    if (lid == 0) warpsum[wid] = partial;
    __syncthreads();
    if (tid == 0) {
        float v = 0.0f;
        #pragma unroll
        for (int w = 0; w < 8; ++w) v += warpsum[w];
        g_partial[blockIdx.x] = v;
        __threadfence();
        const unsigned int t = atomicAdd(&g_ticket, 1u);
        s_last = (t == GRID - 1) ? 1 : 0;
    }
    __syncthreads();

    // last finishing block: fused finalize (replay-safe ticket reset)
    if (s_last) {
        float s = 0.0f;
        for (int i = tid; i < GRID; i += 256)
            s += __ldcg(&g_partial[i]);
        #pragma unroll
        for (int o = 16; o > 0; o >>= 1)
            s += __shfl_down_sync(0xffffffffu, s, o);
        if (lid == 0) warpsum[wid] = s;
        __syncthreads();
        if (tid == 0) {
            float v = 0.0f;
            #pragma unroll
            for (int w = 0; w < 8; ++w) v += warpsum[w];
            out[0] = v;
            g_ticket = 0;
            __threadfence();
        }
    }
}

extern "C" void kernel_launch(void* const* d_in, const int* in_sizes, int n_in,
                              void* d_out, int out_size) {
    const float* A   = (const float*)d_in[0];
    const int* inL   = (const int*)d_in[1];
    const int* tgtL  = (const int*)d_in[2];
    const int* gstep = (const int*)d_in[3];
    float* out       = (float*)d_out;

    gal_main_kernel<<<GRID, 256>>>(A, inL, tgtL, gstep, out);
}

// round 14
// speedup vs baseline: 1.0428x; 1.0428x over previous
#include <cuda_runtime.h>

#define NB 64
#define TD 2048
#define TE 512
#define G_STEPS 20000
#define LN_GAMMA (-5.0001250041667e-05)   // ln(0.99995)
#define LOG2E 1.4426950408889634
#define GRID 888                          // 148 SMs x 6 blocks
#define CHUNK_SHIFT 3                     // 8 rows per unit
#define CHUNKS_PER_B (TD >> CHUNK_SHIFT)  // 256
#define NCHUNK (NB * CHUNKS_PER_B)        // 16384
#define PF_DIST 4                         // prefetch 4 units ahead (~57MB window chip-wide)

__device__ float g_partial[GRID];
__device__ unsigned int g_ticket = 0;     // self-resetting, graph-replay safe

__device__ __forceinline__ float ex2a(float x) {
    float r; asm("ex2.approx.f32 %0, %1;" : "=f"(r) : "f"(x)); return r;
}
__device__ __forceinline__ void pfL2(const float* p) {
    asm volatile("prefetch.global.L2 [%0];" :: "l"(p));
}

__device__ __forceinline__ void gal_acc(float& facc, float4 v, float y,
                                        float a0, float a1, float a2, float a3,
                                        float m1, float m2, float m3, float kneg)
{
    const float d0 = a0 - y, d1 = a1 - y, d2 = a2 - y, d3 = a3 - y;
    const float w0 = 1.0f - ex2a(d0 * d0 * kneg);
    const float w1 = 1.0f - ex2a(d1 * d1 * kneg);
    const float w2 = 1.0f - ex2a(d2 * d2 * kneg);
    const float w3 = 1.0f - ex2a(d3 * d3 * kneg);
    facc = fmaf(w0, v.x, facc);
    facc = fmaf(w1, v.y * m1, facc);
    facc = fmaf(w2, v.z * m2, facc);
    facc = fmaf(w3, v.w * m3, facc);
}

__global__ void __launch_bounds__(256, 6) gal_main_kernel(
    const float* __restrict__ A,      // [NB, TD, TE]
    const int*   __restrict__ inL,    // [NB]
    const int*   __restrict__ tgtL,   // [NB]
    const int*   __restrict__ gstep,  // [1]
    float*       __restrict__ out)    // [1]
{
    __shared__ float s_invL[NB], s_invF[NB], s_scale[NB];
    __shared__ int   s_L[NB], s_F[NB];
    __shared__ float warpsum[8];
    __shared__ int   s_last;

    const int tid = threadIdx.x;
    if (tid < NB) {
        const int L = inL[tid];
        const int F = tgtL[tid];
        s_L[tid] = L;
        s_F[tid] = F;
        s_invL[tid]  = 1.0f / (float)L;
        s_invF[tid]  = 1.0f / (float)F;
        s_scale[tid] = 1.0f / ((float)F * (float)NB);
    }
    __syncthreads();

    float partial = 0.0f;
    const int step = *gstep;

    if (step <= G_STEPS) {
        const double gd = exp((double)step * LN_GAMMA);
        const float kneg = (float)(-(0.5 / (gd * gd)) * LOG2E);

        const int half = tid >> 7;            // 0/1: row parity within the unit
        const int cidx = (tid & 127) << 2;    // float4 column start
        const float fc0 = (float)cidx;

        // warm the prefetch window: first PF_DIST units of this block
        #pragma unroll
        for (int k = 0; k < PF_DIST; ++k) {
            const int chp = blockIdx.x + k * GRID;
            if (chp < NCHUNK) {
                const int bp = chp >> 8;
                const int rp = (chp & (CHUNKS_PER_B - 1)) << CHUNK_SHIFT;
                if (rp < s_F[bp] && cidx < s_L[bp]) {
                    const float* q = A + ((size_t)bp << 20)
                                       + ((size_t)(rp + half) << 9) + cidx;
                    pfL2(q); pfL2(q + 1024); pfL2(q + 2048); pfL2(q + 3072);
                }
            }
        }

        for (int ch = blockIdx.x; ch < NCHUNK; ch += GRID) {
            const int b  = ch >> 8;
            const int r0 = (ch & (CHUNKS_PER_B - 1)) << CHUNK_SHIFT;
            const int F = s_F[b];

            // prefetch PF_DIST units ahead (independent of this unit's validity)
            {
                const int chp = ch + PF_DIST * GRID;
                if (chp < NCHUNK) {
                    const int bp = chp >> 8;
                    const int rp = (chp & (CHUNKS_PER_B - 1)) << CHUNK_SHIFT;
                    if (rp < s_F[bp] && cidx < s_L[bp]) {
                        const float* q = A + ((size_t)bp << 20)
                                           + ((size_t)(rp + half) << 9) + cidx;
                        pfL2(q); pfL2(q + 1024); pfL2(q + 2048); pfL2(q + 3072);
                    }
                }
            }

            if (r0 >= F) continue;
            const int L = s_L[b];
            if (cidx >= L) continue;

            const float invL = s_invL[b];
            const float invF = s_invF[b];
            const float a0 = fc0 * invL;
            const float a1 = (fc0 + 1.0f) * invL;
            const float a2 = (fc0 + 2.0f) * invL;
            const float a3 = (fc0 + 3.0f) * invL;
            const float m1 = (cidx + 1 < L) ? 1.0f : 0.0f;
            const float m2 = (cidx + 2 < L) ? 1.0f : 0.0f;
            const float m3 = (cidx + 3 < L) ? 1.0f : 0.0f;

            const int rows = min(8, F - r0);
            const float* p = A + ((size_t)b << 20) + ((size_t)(r0 + half) << 9) + cidx;
            const float y0 = (float)(r0 + half) * invF;
            const float ys = 2.0f * invF;

            float facc = 0.0f;
            if (rows == 8) {
                // fast path: 4 independent float4 loads front-batched (MLP 4)
                const float4 v0 = __ldg((const float4*)(p));
                const float4 v1 = __ldg((const float4*)(p + 1024));
                const float4 v2 = __ldg((const float4*)(p + 2048));
                const float4 v3 = __ldg((const float4*)(p + 3072));
                gal_acc(facc, v0, y0,            a0, a1, a2, a3, m1, m2, m3, kneg);
                gal_acc(facc, v1, y0 + ys,       a0, a1, a2, a3, m1, m2, m3, kneg);
                gal_acc(facc, v2, y0 + 2.f*ys,   a0, a1, a2, a3, m1, m2, m3, kneg);
                gal_acc(facc, v3, y0 + 3.f*ys,   a0, a1, a2, a3, m1, m2, m3, kneg);
            } else {
                #pragma unroll
                for (int q = 0; q < 4; ++q) {
                    if (half + 2 * q < rows) {
                        const float4 v = __ldg((const float4*)(p + q * 1024));
                        gal_acc(facc, v, y0 + (float)q * ys,
                                a0, a1, a2, a3, m1, m2, m3, kneg);
                    }
                }
            }
            partial = fmaf(facc, s_scale[b], partial);
        }
    }

    // block reduction
    #pragma unroll
    for (int o = 16; o > 0; o >>= 1)
        partial += __shfl_down_sync(0xffffffffu, partial, o);
    const int wid = tid >> 5, lid = tid & 31;
    if (lid == 0) warpsum[wid] = partial;
    __syncthreads();
    if (tid == 0) {
        float v = 0.0f;
        #pragma unroll
        for (int w = 0; w < 8; ++w) v += warpsum[w];
        g_partial[blockIdx.x] = v;
        __threadfence();
        const unsigned int t = atomicAdd(&g_ticket, 1u);
        s_last = (t == GRID - 1) ? 1 : 0;
    }
    __syncthreads();

    // last finishing block: fused finalize (replay-safe ticket reset)
    if (s_last) {
        float s = 0.0f;
        for (int i = tid; i < GRID; i += 256)
            s += __ldcg(&g_partial[i]);
        #pragma unroll
        for (int o = 16; o > 0; o >>= 1)
            s += __shfl_down_sync(0xffffffffu, s, o);
        if (lid == 0) warpsum[wid] = s;
        __syncthreads();
        if (tid == 0) {
            float v = 0.0f;
            #pragma unroll
            for (int w = 0; w < 8; ++w) v += warpsum[w];
            out[0] = v;
            g_ticket = 0;
            __threadfence();
        }
    }
}

extern "C" void kernel_launch(void* const* d_in, const int* in_sizes, int n_in,
                              void* d_out, int out_size) {
    const float* A   = (const float*)d_in[0];
    const int* inL   = (const int*)d_in[1];
    const int* tgtL  = (const int*)d_in[2];
    const int* gstep = (const int*)d_in[3];
    float* out       = (float*)d_out;

    gal_main_kernel<<<GRID, 256>>>(A, inL, tgtL, gstep, out);
}